// round 15
// baseline (speedup 1.0000x reference)
#include <cuda_runtime.h>
#include <cuda_bf16.h>
#include <cstdint>

#define BB 256
#define SS 2048
#define KK 64
#define PF 8      // score prefetch depth (steps)
#define HALF 1024 // steps per half-chain

// Scratch (no allocations allowed in kernel_launch)
// g_Mpack[dir][j][p]: bf16x2 pair for state j, input pair p.
//   dir 0 (fwd): (M[2p][j],   M[2p+1][j])   — column j of M
//   dir 1 (bwd): (M[j][2p],   M[j][2p+1])   — row j of M
__device__ uint32_t g_Mpack[2][KK][32];
__device__ float  g_Af[BB * KK];
__device__ float  g_Bb[BB * KK];
__device__ int    g_cf[BB];
__device__ int    g_cb[BB];
__device__ double g_logZ[BB];
__device__ double g_gold[BB];

static __device__ __forceinline__ float warp_sum(float v) {
#pragma unroll
    for (int o = 16; o > 0; o >>= 1)
        v += __shfl_xor_sync(0xffffffffu, v, o);
    return v;
}

// Dual-column 64-wide matvec in bf16: returns (sum for j0, sum for j0+1).
// W = 32 bf16x2 words (64 states). Mr[0..31] = pairs for j0, Mr[32..63] for j1.
// 4 sub-accumulators per column (depth 8), f32 tree combine.
static __device__ __forceinline__ float2 mv64bf(const uint32_t* W,
                                                const uint32_t (&Mr)[64]) {
    const uint4* W4 = (const uint4*)W;
    __nv_bfloat162 z = __floats2bfloat162_rn(0.f, 0.f);
    __nv_bfloat162 ax0 = z, ax1 = z, ax2 = z, ax3 = z;
    __nv_bfloat162 ay0 = z, ay1 = z, ay2 = z, ay3 = z;
#pragma unroll
    for (int q = 0; q < 8; ++q) {
        uint4 t = W4[q];
        __nv_bfloat162 p0 = *(__nv_bfloat162*)&t.x;
        __nv_bfloat162 p1 = *(__nv_bfloat162*)&t.y;
        __nv_bfloat162 p2 = *(__nv_bfloat162*)&t.z;
        __nv_bfloat162 p3 = *(__nv_bfloat162*)&t.w;
        ax0 = __hfma2(p0, *(const __nv_bfloat162*)&Mr[4 * q + 0], ax0);
        ay0 = __hfma2(p0, *(const __nv_bfloat162*)&Mr[32 + 4 * q + 0], ay0);
        ax1 = __hfma2(p1, *(const __nv_bfloat162*)&Mr[4 * q + 1], ax1);
        ay1 = __hfma2(p1, *(const __nv_bfloat162*)&Mr[32 + 4 * q + 1], ay1);
        ax2 = __hfma2(p2, *(const __nv_bfloat162*)&Mr[4 * q + 2], ax2);
        ay2 = __hfma2(p2, *(const __nv_bfloat162*)&Mr[32 + 4 * q + 2], ay2);
        ax3 = __hfma2(p3, *(const __nv_bfloat162*)&Mr[4 * q + 3], ax3);
        ay3 = __hfma2(p3, *(const __nv_bfloat162*)&Mr[32 + 4 * q + 3], ay3);
    }
    float2 f0 = __bfloat1622float2(ax0), f1 = __bfloat1622float2(ax1);
    float2 f2 = __bfloat1622float2(ax2), f3 = __bfloat1622float2(ax3);
    float sx = (f0.x + f0.y) + (f1.x + f1.y) + (f2.x + f2.y) + (f3.x + f3.y);
    f0 = __bfloat1622float2(ay0); f1 = __bfloat1622float2(ay1);
    f2 = __bfloat1622float2(ay2); f3 = __bfloat1622float2(ay3);
    float sy = (f0.x + f0.y) + (f1.x + f1.y) + (f2.x + f2.y) + (f3.x + f3.y);
    return make_float2(sx, sy);
}

// ---------- kernels ----------
__global__ void init_kernel(const float* __restrict__ T) {
    int i = blockIdx.x * blockDim.x + threadIdx.x;
    if (i >= 2 * KK * 32) return;
    int dir = i >> 11, j = (i >> 5) & 63, p = i & 31;
    float a, b;
    if (dir == 0) { a = expf(T[(2 * p) * KK + j]); b = expf(T[(2 * p + 1) * KK + j]); }
    else          { a = expf(T[j * KK + 2 * p]);   b = expf(T[j * KK + 2 * p + 1]); }
    __nv_bfloat162 h = __floats2bfloat162_rn(a, b);
    g_Mpack[dir][j][p] = *(uint32_t*)&h;
}

// 128 CTAs x 128 threads = 512 fully independent warps, one half-chain each:
// warp 0 = fwd batch 2b, warp 1 = fwd 2b+1, warp 2 = bwd 2b, warp 3 = bwd 2b+1.
// Thread l owns states 2l, 2l+1 (both M slices in 64 bf16x2 regs). Per step:
// 64 HFMA2 + 8 broadcast LDS.128 + 1 STS.32 + __syncwarp — no block barriers.
__global__ void __launch_bounds__(128, 1) main_kernel(
    const float* __restrict__ scores,
    const float* __restrict__ source,
    const float* __restrict__ sink) {
    __shared__ __align__(16) uint32_t sW[4][2][32];  // [warp][parity][pairs]

    const int tid = threadIdx.x, wid = tid >> 5, lane = tid & 31;
    const bool fwd = (wid < 2);
    const int b = (blockIdx.x << 1) + (wid & 1);
    const int j0 = 2 * lane;
    const float* sc = scores + (size_t)b * (SS * KK);
    const float LOG2E = 1.44269504088896340736f;

    // M slices for my two states (bf16x2, 64 regs).
    uint32_t Mr[64];
    {
        const uint32_t* m0 = &g_Mpack[fwd ? 0 : 1][j0][0];
        const uint32_t* m1 = &g_Mpack[fwd ? 0 : 1][j0 + 1][0];
#pragma unroll
        for (int p = 0; p < 32; ++p) { Mr[p] = m0[p]; Mr[32 + p] = m1[p]; }
    }

    const int t0  = fwd ? 0 : SS - 1;
    const int sgn = fwd ? 1 : -1;
    const ptrdiff_t pstep = (ptrdiff_t)sgn * KK;

    // Score prefetch ring (float2: states j0, j0+1) + rolling pointer.
    float2 ring[PF];
#pragma unroll
    for (int k = 0; k < PF; ++k)
        ring[k] = __ldg((const float2*)&sc[(size_t)(t0 + sgn * (1 + k)) * KK + j0]);
    const float* pp = &sc[(size_t)(t0 + sgn * (1 + PF)) * KK + j0];

    // Init: fwd W_0 = exp(source + s_0); bwd = exp(sink + s_{2047}).
    {
        float2 bnd = fwd ? __ldg((const float2*)&source[j0])
                         : __ldg((const float2*)&sink[j0]);
        float2 s0 = __ldg((const float2*)&sc[(size_t)t0 * KK + j0]);
        float w0 = exp2f((bnd.x + s0.x) * LOG2E);
        float w1 = exp2f((bnd.y + s0.y) * LOG2E);
        __nv_bfloat162 h = __floats2bfloat162_rn(w0, w1);
        sW[wid][0][lane] = *(uint32_t*)&h;
    }
    int c = 0;
    __syncwarp();

#pragma unroll 1
    for (int base = 1; base < HALF; base += PF) {
#pragma unroll
        for (int k = 0; k < PF; ++k) {
            const int v = base + k;
            if (v >= HALF) break;          // v = 1..HALF-1 exactly
            const int par = v & 1;
            const uint32_t* W = sW[wid][par ^ 1];

            // Consistent power-of-2 rescale from bf16 exponent of W[0].lo
            // (same shared word on every lane -> bit-identical).
            uint32_t head = W[0];
            int e0 = (int)((head >> 7) & 0xFF);
            float scale = __uint_as_float((uint32_t)(254 - e0) << 23);
            c += e0 - 127;

            float2 sv = ring[k];
            ring[k] = __ldg((const float2*)pp);
            pp += pstep;

            float2 s = mv64bf(W, Mr);
            float es0 = exp2f(sv.x * LOG2E);
            float es1 = exp2f(sv.y * LOG2E);
            float o0 = s.x * (es0 * scale);
            float o1 = s.y * (es1 * scale);

            if (fwd && v == HALF - 1) {        // alpha_{1023} (scaled), f32
                g_Af[(size_t)b * KK + j0]     = o0;
                g_Af[(size_t)b * KK + j0 + 1] = o1;
            }
            __nv_bfloat162 h = __floats2bfloat162_rn(o0, o1);
            sW[wid][par][lane] = *(uint32_t*)&h;
            __syncwarp();
        }
    }

    if (fwd) {
        if (lane == 0) g_cf[b] = c;
    } else {
        // beta'_{1023} = M * Bv_{1024} (no es), one extra renormalized matvec.
        const uint32_t* W = sW[wid][1];        // last write was parity 1
        uint32_t head = W[0];
        int e0 = (int)((head >> 7) & 0xFF);
        float scale = __uint_as_float((uint32_t)(254 - e0) << 23);
        c += e0 - 127;
        float2 s = mv64bf(W, Mr);
        g_Bb[(size_t)b * KK + j0]     = s.x * scale;
        g_Bb[(size_t)b * KK + j0 + 1] = s.y * scale;
        if (lane == 0) g_cb[b] = c;
    }
}

// logZ_b = log(sum_j Af[b][j]*Bb[b][j]) + (cf+cb)*ln2
__global__ __launch_bounds__(64) void combine_kernel() {
    __shared__ float sRed[2];
    const int b = blockIdx.x, j = threadIdx.x;
    float v = g_Af[b * KK + j] * g_Bb[b * KK + j];
    float ws = warp_sum(v);
    if ((j & 31) == 0) sRed[j >> 5] = ws;
    __syncthreads();
    if (j == 0) {
        float tot = sRed[0] + sRed[1];
        g_logZ[b] = ((double)log2f(tot) + (double)(g_cf[b] + g_cb[b])) *
                    0.69314718055994530942;
    }
}

__global__ __launch_bounds__(256) void gold_kernel(
    const float* __restrict__ scores,
    const int* __restrict__ states,
    const float* __restrict__ T,
    const float* __restrict__ source,
    const float* __restrict__ sink) {
    __shared__ float red[256];
    const int b = blockIdx.x, tid = threadIdx.x;
    const int*   st = states + (size_t)b * SS;
    const float* sc = scores + (size_t)b * (SS * KK);

    float acc = 0.f;
    for (int t = tid; t < SS; t += 256) {
        int s0 = __ldg(&st[t]);
        acc += __ldg(&sc[t * KK + s0]);
        if (t + 1 < SS) acc += __ldg(&T[s0 * KK + __ldg(&st[t + 1])]);
    }
    red[tid] = acc;
    __syncthreads();
#pragma unroll
    for (int off = 128; off > 0; off >>= 1) {
        if (tid < off) red[tid] += red[tid + off];
        __syncthreads();
    }
    if (tid == 0)
        g_gold[b] = (double)red[0] + (double)__ldg(&source[__ldg(&st[0])]) +
                    (double)__ldg(&sink[__ldg(&st[SS - 1])]);
}

__global__ __launch_bounds__(256) void finalize_kernel(float* __restrict__ out) {
    __shared__ double red[256];
    const int tid = threadIdx.x;
    red[tid] = g_logZ[tid] - g_gold[tid];
    __syncthreads();
#pragma unroll
    for (int off = 128; off > 0; off >>= 1) {
        if (tid < off) red[tid] += red[tid + off];
        __syncthreads();
    }
    if (tid == 0) *out = (float)(red[0] * (1.0 / BB));
}

extern "C" void kernel_launch(void* const* d_in, const int* in_sizes, int n_in,
                              void* d_out, int out_size) {
    const float* scores = (const float*)d_in[0];   // [B,S,K] f32
    const int*   states = (const int*)d_in[1];     // [B,S] i32
    const float* T      = (const float*)d_in[2];   // [K,K] f32
    const float* source = (const float*)d_in[3];   // [K] f32
    const float* sink   = (const float*)d_in[4];   // [K] f32
    float* out = (float*)d_out;

    init_kernel<<<16, 256>>>(T);
    main_kernel<<<BB / 2, 128>>>(scores, source, sink);
    gold_kernel<<<BB, 256>>>(scores, states, T, source, sink);
    combine_kernel<<<BB, 64>>>();
    finalize_kernel<<<1, 256>>>(out);
}

// round 16
// speedup vs baseline: 1.6047x; 1.6047x over previous
#include <cuda_runtime.h>

#define BB 256
#define SS 2048
#define KK 64
#define PF 8      // score prefetch depth (steps)
#define HALF 1024 // steps per half-chain

// Scratch (no allocations allowed in kernel_launch)
__device__ float  g_M[KK * KK];   // exp(transition)
__device__ float  g_Af[BB * KK];  // forward alpha at t=HALF-1 (scaled)
__device__ float  g_Bb[BB * KK];  // backward beta' at t=HALF-1 (scaled)
__device__ int    g_cf[BB];       // forward exponent offset (log2 units)
__device__ int    g_cb[BB];       // backward exponent offset
__device__ double g_logZ[BB];
__device__ double g_gold[BB];

// ---------- packed f32x2 helpers (Blackwell FFMA2 path, PTX-only) ----------
__device__ __forceinline__ unsigned long long fma2(unsigned long long a,
                                                   unsigned long long b,
                                                   unsigned long long c) {
    unsigned long long d;
    asm("fma.rn.f32x2 %0, %1, %2, %3;" : "=l"(d) : "l"(a), "l"(b), "l"(c));
    return d;
}
__device__ __forceinline__ unsigned long long add2(unsigned long long a,
                                                   unsigned long long b) {
    unsigned long long d;
    asm("add.rn.f32x2 %0, %1, %2;" : "=l"(d) : "l"(a), "l"(b));
    return d;
}
__device__ __forceinline__ float2 unpack2(unsigned long long v) {
    float2 r;
    asm("mov.b64 {%0, %1}, %2;" : "=f"(r.x), "=f"(r.y) : "l"(v));
    return r;
}
__device__ __forceinline__ unsigned long long pack2(float lo, float hi) {
    unsigned long long r;
    asm("mov.b64 %0, {%1, %2};" : "=l"(r) : "f"(lo), "f"(hi));
    return r;
}
__device__ __forceinline__ float warp_sum(float v) {
#pragma unroll
    for (int o = 16; o > 0; o >>= 1)
        v += __shfl_xor_sync(0xffffffffu, v, o);
    return v;
}

// 64-wide matvec partial: sum_i A[i]*Mreg[i] (paired), 4 accumulator chains.
__device__ __forceinline__ float matvec64(const ulonglong2* e4,
                                          const unsigned long long* Mreg) {
    unsigned long long a0 = 0ull, a1 = 0ull, a2 = 0ull, a3 = 0ull;
#pragma unroll
    for (int q = 0; q < 16; q += 2) {
        ulonglong2 ea = e4[q];
        ulonglong2 eb = e4[q + 1];
        a0 = fma2(ea.x, Mreg[2 * q + 0], a0);
        a1 = fma2(ea.y, Mreg[2 * q + 1], a1);
        a2 = fma2(eb.x, Mreg[2 * q + 2], a2);
        a3 = fma2(eb.y, Mreg[2 * q + 3], a3);
    }
    a0 = add2(a0, a1);
    a2 = add2(a2, a3);
    a0 = add2(a0, a2);
    float2 ac = unpack2(a0);
    return ac.x + ac.y;
}

// Power-of-2 renormalizer from a shared word (bit-identical on all threads).
__device__ __forceinline__ float renorm(float head, int& c) {
    int e0 = (int)((__float_as_uint(head) >> 23) & 0xFF);
    c += e0 - 127;
    return __uint_as_float((unsigned)(254 - e0) << 23);
}

// ---------- kernels ----------
__global__ void init_kernel(const float* __restrict__ T) {
    int i = blockIdx.x * blockDim.x + threadIdx.x;
    if (i < KK * KK) g_M[i] = expf(T[i]);
}

// 256 CTAs x 64 threads (2 warps -> SMSP 0/1; ~3.46 CTAs/SM stack deep and
// hide the serial step chain — the R3-measured regime). CTA p < 128: FORWARD
// halves of batches 2p, 2p+1. CTA >= 128: BACKWARD halves of the same pair.
// Both batches share one M-slice in registers; the dual matvec amortizes the
// barrier + serial latency over two chain-steps (R12-proven math).
__global__ void __launch_bounds__(64, 8) main_kernel(
    const float* __restrict__ scores,
    const float* __restrict__ source,
    const float* __restrict__ sink) {
    __shared__ __align__(16) float sA[2][2][KK];  // [batch][parity][state]

    const int j    = threadIdx.x;          // state owned by this thread
    const bool fwd = (blockIdx.x < 128);
    const int pr   = fwd ? blockIdx.x : blockIdx.x - 128;
    const int b0   = pr << 1;              // batches b0, b0+1
    const float* sc0 = scores + (size_t)b0 * (SS * KK);
    const float* sc1 = sc0 + (size_t)SS * KK;

    const float LOG2E = 1.44269504088896340736f;

    // M slice in registers (shared by both batches):
    // forward = column j (stride KK), backward = row j (stride 1).
    const int m0 = fwd ? j : j * KK;
    const int ms = fwd ? KK : 1;
    unsigned long long Mreg[32];
#pragma unroll
    for (int p = 0; p < 32; ++p)
        Mreg[p] = pack2(g_M[m0 + (2 * p) * ms], g_M[m0 + (2 * p + 1) * ms]);

    const int t0  = fwd ? 0 : SS - 1;
    const int sgn = fwd ? 1 : -1;
    const ptrdiff_t pstep = (ptrdiff_t)sgn * KK;

    // Score prefetch rings + rolling refill pointers.
    float ring0[PF], ring1[PF];
#pragma unroll
    for (int k = 0; k < PF; ++k) {
        ring0[k] = __ldg(&sc0[(size_t)(t0 + sgn * (1 + k)) * KK + j]);
        ring1[k] = __ldg(&sc1[(size_t)(t0 + sgn * (1 + k)) * KK + j]);
    }
    const float* pp0 = sc0 + (size_t)(t0 + sgn * (1 + PF)) * KK + j;
    const float* pp1 = sc1 + (size_t)(t0 + sgn * (1 + PF)) * KK + j;

    // Init: fwd A_0 = exp(source + s_0); bwd Bv = exp(sink + s_{2047}).
    float bnd = fwd ? __ldg(&source[j]) : __ldg(&sink[j]);
    float A0 = exp2f((bnd + __ldg(&sc0[(size_t)t0 * KK + j])) * LOG2E);
    float A1 = exp2f((bnd + __ldg(&sc1[(size_t)t0 * KK + j])) * LOG2E);
    int c0 = 0, c1 = 0;
    sA[0][0][j] = A0;
    sA[1][0][j] = A1;
    __syncthreads();

#pragma unroll 1
    for (int base = 1; base < HALF; base += PF) {
#pragma unroll
        for (int k = 0; k < PF; ++k) {
            const int v = base + k;
            if (v >= HALF) break;          // run v = 1..HALF-1 exactly
            const int par = v & 1;

            // es for this step (rows loaded PF steps ago); rolling refills.
            float es0 = exp2f(ring0[k] * LOG2E);
            float es1 = exp2f(ring1[k] * LOG2E);
            ring0[k] = __ldg(pp0); pp0 += pstep;
            ring1[k] = __ldg(pp1); pp1 += pstep;

            // Per-batch consistent power-of-2 rescale.
            float sc_a = renorm(sA[0][par ^ 1][0], c0);
            float sc_b = renorm(sA[1][par ^ 1][0], c1);

            float sum0 = matvec64(
                reinterpret_cast<const ulonglong2*>(sA[0][par ^ 1]), Mreg);
            float sum1 = matvec64(
                reinterpret_cast<const ulonglong2*>(sA[1][par ^ 1]), Mreg);

            A0 = sum0 * (es0 * sc_a);
            A1 = sum1 * (es1 * sc_b);
            sA[0][par][j] = A0;
            sA[1][par][j] = A1;
            __syncthreads();
        }
    }
    // Loop ran v = 1..1023; last write was to parity 1.

    if (fwd) {
        g_Af[(b0 + 0) * KK + j] = A0;      // alpha_{1023}, scaled 2^-c
        g_Af[(b0 + 1) * KK + j] = A1;
        if (j == 0) { g_cf[b0] = c0; g_cf[b0 + 1] = c1; }
    } else {
        // beta'_{1023} = M * Bv_{1024} (no es), one extra renormalized matvec.
        float sc_a = renorm(sA[0][1][0], c0);
        float sc_b = renorm(sA[1][1][0], c1);
        float sum0 = matvec64(
            reinterpret_cast<const ulonglong2*>(sA[0][1]), Mreg);
        float sum1 = matvec64(
            reinterpret_cast<const ulonglong2*>(sA[1][1]), Mreg);
        g_Bb[(b0 + 0) * KK + j] = sum0 * sc_a;
        g_Bb[(b0 + 1) * KK + j] = sum1 * sc_b;
        if (j == 0) { g_cb[b0] = c0; g_cb[b0 + 1] = c1; }
    }
}

// logZ_b = log(sum_j Af[b][j]*Bb[b][j]) + (cf+cb)*ln2
__global__ __launch_bounds__(64) void combine_kernel() {
    __shared__ float sRed[2];
    const int b = blockIdx.x, j = threadIdx.x;
    float v = g_Af[b * KK + j] * g_Bb[b * KK + j];
    float ws = warp_sum(v);
    if ((j & 31) == 0) sRed[j >> 5] = ws;
    __syncthreads();
    if (j == 0) {
        float tot = sRed[0] + sRed[1];
        g_logZ[b] = ((double)log2f(tot) + (double)(g_cf[b] + g_cb[b])) *
                    0.69314718055994530942;
    }
}

__global__ __launch_bounds__(256) void gold_kernel(
    const float* __restrict__ scores,
    const int* __restrict__ states,
    const float* __restrict__ T,
    const float* __restrict__ source,
    const float* __restrict__ sink) {
    __shared__ float red[256];
    const int b = blockIdx.x, tid = threadIdx.x;
    const int*   st = states + (size_t)b * SS;
    const float* sc = scores + (size_t)b * (SS * KK);

    float acc = 0.f;
    for (int t = tid; t < SS; t += 256) {
        int s0 = __ldg(&st[t]);
        acc += __ldg(&sc[t * KK + s0]);
        if (t + 1 < SS) acc += __ldg(&T[s0 * KK + __ldg(&st[t + 1])]);
    }
    red[tid] = acc;
    __syncthreads();
#pragma unroll
    for (int off = 128; off > 0; off >>= 1) {
        if (tid < off) red[tid] += red[tid + off];
        __syncthreads();
    }
    if (tid == 0)
        g_gold[b] = (double)red[0] + (double)__ldg(&source[__ldg(&st[0])]) +
                    (double)__ldg(&sink[__ldg(&st[SS - 1])]);
}

__global__ __launch_bounds__(256) void finalize_kernel(float* __restrict__ out) {
    __shared__ double red[256];
    const int tid = threadIdx.x;
    red[tid] = g_logZ[tid] - g_gold[tid];
    __syncthreads();
#pragma unroll
    for (int off = 128; off > 0; off >>= 1) {
        if (tid < off) red[tid] += red[tid + off];
        __syncthreads();
    }
    if (tid == 0) *out = (float)(red[0] * (1.0 / BB));
}

extern "C" void kernel_launch(void* const* d_in, const int* in_sizes, int n_in,
                              void* d_out, int out_size) {
    const float* scores = (const float*)d_in[0];   // [B,S,K] f32
    const int*   states = (const int*)d_in[1];     // [B,S] i32
    const float* T      = (const float*)d_in[2];   // [K,K] f32
    const float* source = (const float*)d_in[3];   // [K] f32
    const float* sink   = (const float*)d_in[4];   // [K] f32
    float* out = (float*)d_out;

    init_kernel<<<16, 256>>>(T);
    main_kernel<<<2 * (BB / 2), 64>>>(scores, source, sink);
    gold_kernel<<<BB, 256>>>(scores, states, T, source, sink);
    combine_kernel<<<BB, 64>>>();
    finalize_kernel<<<1, 256>>>(out);
}